// round 5
// baseline (speedup 1.0000x reference)
#include <cuda_runtime.h>
#include <cuda_bf16.h>

#define NMAX 100000
#define EMAX 1700000
#define FDIM 128
#define HDIM 64

// ---------------- scratch (static device globals; no runtime alloc) -------
__device__ int   d_is32;                 // 1 if edge buffers are int32
__device__ int   d_deg[NMAX];
__device__ float d_dinv[NMAX];
__device__ float d_G   [NMAX * HDIM];    // g1, then g2 (reused)
__device__ float d_ACC [NMAX * HDIM];    // acc1, then TD (reused)
__device__ float d_ACC2[NMAX * HDIM];    // acc2
__device__ float d_H   [NMAX * HDIM];    // H1, then H2 (reused)
__device__ float d_Wc  [FDIM * HDIM];    // W0 @ W1
__device__ float d_bc  [HDIM];           // b0 @ W1
__device__ float d_WbT [HDIM * HDIM];    // Wb[0]^T
__device__ int   d_EPRED[2 * EMAX];      // normalized int32 prediction edges
__device__ int   d_EPOS [2 * EMAX];      // normalized int32 message edges

// ---------------- vector reduction helper ----------------------------------
__device__ __forceinline__ void red_add_v4(float* p, float4 v) {
#if __CUDA_ARCH__ >= 900
    asm volatile("red.global.add.v4.f32 [%0], {%1, %2, %3, %4};"
                 :: "l"(p), "f"(v.x), "f"(v.y), "f"(v.z), "f"(v.w)
                 : "memory");
#else
    atomicAdd(p + 0, v.x); atomicAdd(p + 1, v.y);
    atomicAdd(p + 2, v.z); atomicAdd(p + 3, v.w);
#endif
}

// ---------------- zero accumulators + flag ---------------------------------
__global__ void __launch_bounds__(256) k_zero(int n) {
    int i = blockIdx.x * blockDim.x + threadIdx.x;   // 0 .. n*16-1
    if (i == 0) d_is32 = 0;
    if (i < n) d_deg[i] = 0;
    if (i < n * 16) {
        float4 z = make_float4(0.f, 0.f, 0.f, 0.f);
        ((float4*)d_ACC )[i] = z;
        ((float4*)d_ACC2)[i] = z;
    }
}

// ---------------- edge dtype detection -------------------------------------
// Reads only the first 2E 32-bit words (full buffer if int32; first E values
// if int64). int64 little-endian with ids < 2^31 => every odd word == 0.
__global__ void __launch_bounds__(256) k_detect(const unsigned int* __restrict__ w,
                                                int nwords2) {
    int i = blockIdx.x * blockDim.x + threadIdx.x;
    int idx = 2 * i + 1;
    if (idx < nwords2 && w[idx] != 0u) d_is32 = 1;   // racy all-write-same: fine
}

// ---------------- normalize edges to int32 ---------------------------------
template <int WHICH>   // 0 -> d_EPRED, 1 -> d_EPOS
__global__ void __launch_bounds__(256) k_norm(const int* __restrict__ buf, int n2) {
    int i = blockIdx.x * blockDim.x + threadIdx.x;
    if (i >= n2) return;
    int v = d_is32 ? buf[i] : buf[2 * i];   // int64 LE: take low word
    (WHICH == 0 ? d_EPRED : d_EPOS)[i] = v;
}

// ---------------- degree (self-loop added in dinv) ------------------------
__global__ void __launch_bounds__(256) k_deg(int E) {
    int i = blockIdx.x * blockDim.x + threadIdx.x;
    if (i < E) atomicAdd(&d_deg[d_EPOS[E + i]], 1);   // col = target
}

__global__ void __launch_bounds__(256) k_dinv(int n) {
    int i = blockIdx.x * blockDim.x + threadIdx.x;
    if (i < n) d_dinv[i] = rsqrtf((float)(d_deg[i] + 1));  // +1 self loop
}

// ---------------- tiny weight prep: Wc = W0@W1, bc = b0@W1, WbT -----------
__global__ void __launch_bounds__(256) k_prep(const float* __restrict__ W0,
                                              const float* __restrict__ b0,
                                              const float* __restrict__ W1,
                                              const float* __restrict__ Wb) {
    int t = blockIdx.x * blockDim.x + threadIdx.x;
    if (t < FDIM * HDIM) {
        int k = t / HDIM, o = t % HDIM;
        float s = 0.f;
        #pragma unroll 8
        for (int m = 0; m < FDIM; m++) s += W0[k * FDIM + m] * W1[m * HDIM + o];
        d_Wc[t] = s;
    }
    if (t < HDIM) {
        float s = 0.f;
        for (int m = 0; m < FDIM; m++) s += b0[m] * W1[m * HDIM + t];
        d_bc[t] = s;
    }
    if (t < HDIM * HDIM) {
        int i = t / HDIM, j = t % HDIM;
        d_WbT[j * HDIM + i] = Wb[t];   // WbT[j][i] = Wb[i][j]
    }
}

// ---------------- tiled fp32 GEMM: C[M,64] = A[M,K] @ B[K,64] -------------
//   AG: 0 = Ain param, 1 = d_H
//   BG: 0 = Bin param, 1 = d_Wc, 2 = d_WbT
//   CG: 1 = d_G, 2 = d_ACC
//   BIASG: 0 = none, 1 = d_bc
//   SCALE: multiply each output row by d_dinv[row]
template <int K, int AG, int BG, int CG, int BIASG, int SCALE>
__global__ void __launch_bounds__(256) gemm64(const float* __restrict__ Ain,
                                              const float* __restrict__ Bin,
                                              int M) {
    const float* A = (AG == 1) ? d_H : Ain;
    const float* B = (BG == 1) ? d_Wc : (BG == 2) ? d_WbT : Bin;
    float*       C = (CG == 1) ? d_G : d_ACC;

    __shared__ float Bs[K][68];     // padded rows (272B = 17*16B, keeps 16B align)
    __shared__ float As[16][68];    // transposed chunk: [k][row]
    const int tid = threadIdx.x;

    for (int idx = tid; idx < K * 16; idx += 256) {
        int k = idx >> 4, c4 = (idx & 15) << 2;
        float4 v = *(const float4*)(B + k * 64 + c4);
        *(float4*)&Bs[k][c4] = v;
    }

    const int bm = blockIdx.x * 64;
    const int tr = tid >> 4;            // 0..15 (row group)
    const int tc = tid & 15;            // 0..15 (col group)
    const int lrow = tid >> 2;          // 0..63 (A-load row)
    const int lk   = (tid & 3) << 2;    // 0,4,8,12 (A-load k)

    float acc[4][4] = {};

    for (int kc = 0; kc < K; kc += 16) {
        float4 av = make_float4(0.f, 0.f, 0.f, 0.f);
        int grow = bm + lrow;
        if (grow < M) av = *(const float4*)(A + (size_t)grow * K + kc + lk);
        __syncthreads();                        // prev chunk consumed (also fences Bs)
        As[lk + 0][lrow] = av.x;
        As[lk + 1][lrow] = av.y;
        As[lk + 2][lrow] = av.z;
        As[lk + 3][lrow] = av.w;
        __syncthreads();
        #pragma unroll
        for (int k = 0; k < 16; k++) {
            float4 a = *(const float4*)&As[k][tr * 4];
            float4 b = *(const float4*)&Bs[kc + k][tc * 4];
            acc[0][0] += a.x * b.x; acc[0][1] += a.x * b.y; acc[0][2] += a.x * b.z; acc[0][3] += a.x * b.w;
            acc[1][0] += a.y * b.x; acc[1][1] += a.y * b.y; acc[1][2] += a.y * b.z; acc[1][3] += a.y * b.w;
            acc[2][0] += a.z * b.x; acc[2][1] += a.z * b.y; acc[2][2] += a.z * b.z; acc[2][3] += a.z * b.w;
            acc[3][0] += a.w * b.x; acc[3][1] += a.w * b.y; acc[3][2] += a.w * b.z; acc[3][3] += a.w * b.w;
        }
    }

    #pragma unroll
    for (int i = 0; i < 4; i++) {
        int r = bm + tr * 4 + i;
        if (r >= M) continue;
        float s = SCALE ? d_dinv[r] : 1.f;
        #pragma unroll
        for (int j = 0; j < 4; j++) {
            float v = acc[i][j];
            if (BIASG == 1) v += d_bc[tc * 4 + j];
            C[r * 64 + tc * 4 + j] = v * s;
        }
    }
}

// ---------------- edge scatter-add: acc[col] += g[row] --------------------
// 16 threads per edge, float4 gather, ONE red.global.add.v4.f32 each.
// Grid-stride with bounded grid.
template <int WHICH>   // 1 -> d_ACC, 2 -> d_ACC2
__global__ void __launch_bounds__(256) k_scatter(int E) {
    int total = E * 16;
    for (int t = blockIdx.x * blockDim.x + threadIdx.x; t < total;
         t += gridDim.x * blockDim.x) {
        int e = t >> 4, c = t & 15;
        int r  = d_EPOS[e];
        int cl = d_EPOS[E + e];
        float4 v = *(const float4*)(d_G + (size_t)r * 64 + c * 4);
        float* p = (WHICH == 1 ? d_ACC : d_ACC2) + (size_t)cl * 64 + c * 4;
        red_add_v4(p, v);
    }
}

// ---------------- finalize: H = [relu](dinv*(acc+g) + b) ------------------
template <int WHICH, int RELU>   // WHICH: 1 -> d_ACC, 2 -> d_ACC2
__global__ void __launch_bounds__(256) k_fin(const float* __restrict__ b, int n64) {
    int i = blockIdx.x * blockDim.x + threadIdx.x;
    if (i >= n64) return;
    const float* acc = (WHICH == 1) ? d_ACC : d_ACC2;
    int n = i >> 6, f = i & 63;
    float v = d_dinv[n] * (acc[i] + d_G[i]) + b[f];
    if (RELU) v = fmaxf(v, 0.f);
    d_H[i] = v;
}

// ---------------- bilinear decoder: out[e] = H2[src]·TD[dst] + bb ---------
__global__ void __launch_bounds__(256) k_bilinear(int E, const float* __restrict__ bb,
                                                  float* __restrict__ out) {
    int total = E * 16;
    for (int t = blockIdx.x * blockDim.x + threadIdx.x; t < total;
         t += gridDim.x * blockDim.x) {
        int e = t >> 4, c = t & 15;
        int s = d_EPRED[e];
        int d = d_EPRED[E + e];
        float4 a = *(const float4*)(d_H   + (size_t)s * 64 + c * 4);
        float4 b = *(const float4*)(d_ACC + (size_t)d * 64 + c * 4);  // d_ACC = TD
        float p = a.x * b.x + a.y * b.y + a.z * b.z + a.w * b.w;
        p += __shfl_xor_sync(0xffffffffu, p, 8);
        p += __shfl_xor_sync(0xffffffffu, p, 4);
        p += __shfl_xor_sync(0xffffffffu, p, 2);
        p += __shfl_xor_sync(0xffffffffu, p, 1);
        if (c == 0) out[e] = p + bb[0];
    }
}

// ---------------- launcher: kernel launches ONLY ---------------------------
extern "C" void kernel_launch(void* const* d_in, const int* in_sizes, int n_in,
                              void* d_out, int out_size) {
    const float* x     = (const float*)d_in[0];
    const int*   eip   = (const int*)d_in[1];    // prediction edges (raw words)
    const int*   eipos = (const int*)d_in[2];    // message edges (raw words)
    const float* W0    = (const float*)d_in[3];
    const float* b0    = (const float*)d_in[4];
    const float* W1    = (const float*)d_in[5];
    const float* b1    = (const float*)d_in[6];
    const float* W2    = (const float*)d_in[7];
    const float* b2    = (const float*)d_in[8];
    const float* Wb    = (const float*)d_in[9];
    const float* bb    = (const float*)d_in[10];
    float* out = (float*)d_out;

    const int N     = in_sizes[0] / FDIM;
    const int Epred = in_sizes[1] / 2;
    const int Epos  = in_sizes[2] / 2;
    const int GS    = 8192;   // bounded grid for edge-parallel kernels

    // zero + dtype detect + normalize edges to int32
    k_zero<<<(N * 16 + 255) / 256, 256>>>(N);
    k_detect<<<(Epred + 255) / 256, 256>>>((const unsigned int*)eip, 2 * Epred);
    k_norm<0><<<(2 * Epred + 255) / 256, 256>>>(eip, 2 * Epred);
    k_norm<1><<<(2 * Epos  + 255) / 256, 256>>>(eipos, 2 * Epos);

    // degree + normalization (shared by both convs)
    k_deg<<<(Epos + 255) / 256, 256>>>(Epos);
    k_dinv<<<(N + 255) / 256, 256>>>(N);

    // weight prep: Wc = W0@W1, bc = b0@W1, WbT
    k_prep<<<32, 256>>>(W0, b0, W1, Wb);

    // g1 = (x @ Wc + bc) * dinv[row]
    gemm64<FDIM, 0, 1, 1, 1, 1><<<(N + 63) / 64, 256>>>(x, nullptr, N);

    // conv1 aggregate: acc1[col] += g1[row]
    k_scatter<1><<<GS, 256>>>(Epos);

    // H1 = relu(dinv*(acc1 + g1) + b1)
    k_fin<1, 1><<<(N * HDIM + 255) / 256, 256>>>(b1, N * HDIM);

    // g2 = (H1 @ W2) * dinv[row]
    gemm64<HDIM, 1, 0, 1, 0, 1><<<(N + 63) / 64, 256>>>(nullptr, W2, N);

    // conv2 aggregate
    k_scatter<2><<<GS, 256>>>(Epos);

    // H2 = dinv*(acc2 + g2) + b2   (no relu)
    k_fin<2, 0><<<(N * HDIM + 255) / 256, 256>>>(b2, N * HDIM);

    // TD = H2 @ Wb^T   (stored in d_ACC; acc1 dead now)
    gemm64<HDIM, 1, 2, 2, 0, 0><<<(N + 63) / 64, 256>>>(nullptr, nullptr, N);

    // logits[e] = H2[src] · TD[dst] + bb
    k_bilinear<<<GS, 256>>>(Epred, bb, out);
}